// round 3
// baseline (speedup 1.0000x reference)
#include <cuda_runtime.h>

#define IN_DIM 128
#define OUT_DIM 64
#define MAX_N 50000
#define MAX_E 800000
#define ALPHA_LEAKY 0.2f
#define EPS_F 1e-10f

// ---- scratch (no allocation allowed -> device globals) ----
__device__ float g_h[(size_t)MAX_N * OUT_DIM];     // 12.8 MB
__device__ float g_ssrc[MAX_N];
__device__ float g_stgt[MAX_N];
__device__ int   g_emax[MAX_N];                    // ordered-int encoded float max
__device__ float g_esum[MAX_N];
__device__ float g_e[MAX_E];                       // per-edge score, then exp

// ordered-int encoding: signed atomicMax on enc(f) == float max
__device__ __forceinline__ int enc_f(float f) {
    int i = __float_as_int(f);
    return (i < 0) ? (i ^ 0x7fffffff) : i;
}
__device__ __forceinline__ float dec_f(int v) {
    if (v < 0) v ^= 0x7fffffff;
    return __int_as_float(v);
}

// enc(-inf) = 0xFF800000 ^ 0x7FFFFFFF = 0x807FFFFF
#define ENC_NEG_INF ((int)0x807FFFFF)

__global__ void init_kernel(int n) {
    int i = blockIdx.x * blockDim.x + threadIdx.x;
    if (i < n) {
        g_emax[i] = ENC_NEG_INF;
        g_esum[i] = 0.0f;
    }
}

// ---------------------------------------------------------------------------
// GEMM: g_h[n][o] = sum_k X[n][k] * W[o][k]
// Tile: 64 nodes x 64 outs per block, 256 threads, each thread 4x4 register tile.
// ---------------------------------------------------------------------------
#define WT_PITCH (OUT_DIM + 4)   // 68
#define XS_PITCH (IN_DIM + 4)    // 132
#define GEMM_SMEM_BYTES ((IN_DIM * WT_PITCH + 64 * XS_PITCH) * (int)sizeof(float))

__global__ void __launch_bounds__(256) gemm_kernel(
    const float* __restrict__ X, const float* __restrict__ Wg, int N)
{
    extern __shared__ float sm[];
    float* Wt = sm;                              // [IN_DIM][WT_PITCH]
    float* Xs = sm + IN_DIM * WT_PITCH;          // [64][XS_PITCH]

    int t = threadIdx.x;

    // load W transposed: Wt[k][o] = Wg[o*128 + k]
    for (int i = t; i < IN_DIM * OUT_DIM; i += 256) {
        int o = i >> 7;
        int k = i & 127;
        Wt[k * WT_PITCH + o] = Wg[i];
    }

    // load 64-node X tile (float4 coalesced)
    int n0 = blockIdx.x * 64;
    for (int i = t; i < 64 * 32; i += 256) {
        int n  = i >> 5;       // 0..63
        int kq = i & 31;       // float4 index within row
        int gn = n0 + n;
        float4 v = make_float4(0.f, 0.f, 0.f, 0.f);
        if (gn < N) v = ((const float4*)(X + (size_t)gn * IN_DIM))[kq];
        ((float4*)(Xs + n * XS_PITCH))[kq] = v;
    }
    __syncthreads();

    int oq = (t & 15);         // out quad index 0..15
    int nq = (t >> 4) * 4;     // node base 0,4,...,60

    float acc[4][4];
#pragma unroll
    for (int j = 0; j < 4; j++)
#pragma unroll
        for (int c = 0; c < 4; c++) acc[j][c] = 0.0f;

#pragma unroll 8
    for (int k = 0; k < IN_DIM; k++) {
        float4 w4 = ((const float4*)(Wt + k * WT_PITCH))[oq];
#pragma unroll
        for (int j = 0; j < 4; j++) {
            float x = Xs[(nq + j) * XS_PITCH + k];
            acc[j][0] = fmaf(x, w4.x, acc[j][0]);
            acc[j][1] = fmaf(x, w4.y, acc[j][1]);
            acc[j][2] = fmaf(x, w4.z, acc[j][2]);
            acc[j][3] = fmaf(x, w4.w, acc[j][3]);
        }
    }

#pragma unroll
    for (int j = 0; j < 4; j++) {
        int gn = n0 + nq + j;
        if (gn < N) {
            float4 v = make_float4(acc[j][0], acc[j][1], acc[j][2], acc[j][3]);
            ((float4*)(g_h + (size_t)gn * OUT_DIM))[oq] = v;
        }
    }
}

// ---------------------------------------------------------------------------
// per-node attention partial scores: one warp per node, shuffle reduce
// ---------------------------------------------------------------------------
__global__ void score_kernel(const float* __restrict__ a, int N) {
    int warp = (blockIdx.x * blockDim.x + threadIdx.x) >> 5;
    int lane = threadIdx.x & 31;
    if (warp >= N) return;
    const float* hr = g_h + (size_t)warp * OUT_DIM;
    float h0 = hr[lane];
    float h1 = hr[lane + 32];
    float ss = h0 * __ldg(a + lane)      + h1 * __ldg(a + lane + 32);
    float st = h0 * __ldg(a + 64 + lane) + h1 * __ldg(a + 96 + lane);
#pragma unroll
    for (int off = 16; off > 0; off >>= 1) {
        ss += __shfl_down_sync(0xffffffffu, ss, off);
        st += __shfl_down_sync(0xffffffffu, st, off);
    }
    if (lane == 0) {
        g_ssrc[warp] = ss;
        g_stgt[warp] = st;
    }
}

// ---------------------------------------------------------------------------
// edge pass 1: e = leaky_relu(s_src[src] + s_tgt[tgt]); segment max over tgt
// edge_index is INT32 (JAX x64 disabled canonicalizes int64 -> int32).
// ---------------------------------------------------------------------------
__global__ void edge1_kernel(const int* __restrict__ ei, int E) {
    int i = blockIdx.x * blockDim.x + threadIdx.x;
    if (i >= E) return;
    int src = __ldg(ei + i);
    int tgt = __ldg(ei + E + i);
    float e = g_ssrc[src] + g_stgt[tgt];
    e = (e > 0.0f) ? e : (ALPHA_LEAKY * e);
    g_e[i] = e;
    atomicMax(&g_emax[tgt], enc_f(e));
}

// ---------------------------------------------------------------------------
// edge pass 2: e_exp = exp(e - max[tgt]); segment sum over tgt
// ---------------------------------------------------------------------------
__global__ void edge2_kernel(const int* __restrict__ ei, int E) {
    int i = blockIdx.x * blockDim.x + threadIdx.x;
    if (i >= E) return;
    int tgt = __ldg(ei + E + i);
    float em = dec_f(g_emax[tgt]);
    float ex = __expf(g_e[i] - em);
    g_e[i] = ex;
    atomicAdd(&g_esum[tgt], ex);
}

// ---------------------------------------------------------------------------
// edge pass 3 (dominant): attention-weighted scatter-add of h[src] into out[tgt]
// 16 lanes per edge, each lane one float4 (64 floats / edge), vector RED.
// ---------------------------------------------------------------------------
__global__ void __launch_bounds__(256) edge3_kernel(
    const int* __restrict__ ei, float* __restrict__ out, int E)
{
    int gid = blockIdx.x * blockDim.x + threadIdx.x;
    int i   = gid >> 4;          // edge id
    int sub = gid & 15;          // float4 chunk within the 64-wide row
    if (i >= E) return;

    int src = __ldg(ei + i);
    int tgt = __ldg(ei + E + i);
    float att = g_e[i] / (g_esum[tgt] + EPS_F);

    float4 h4 = *((const float4*)(g_h + (size_t)src * OUT_DIM) + sub);
    float4 v = make_float4(h4.x * att, h4.y * att, h4.z * att, h4.w * att);

    float* addr = out + (size_t)tgt * OUT_DIM + sub * 4;
    asm volatile("red.global.add.v4.f32 [%0], {%1,%2,%3,%4};"
                 :: "l"(addr), "f"(v.x), "f"(v.y), "f"(v.z), "f"(v.w)
                 : "memory");
}

// ---------------------------------------------------------------------------
// ELU epilogue (in place on d_out)
// ---------------------------------------------------------------------------
__global__ void elu_kernel(float* __restrict__ out, int n4) {
    int i = blockIdx.x * blockDim.x + threadIdx.x;
    if (i >= n4) return;
    float4 v = ((float4*)out)[i];
    v.x = (v.x > 0.0f) ? v.x : expm1f(v.x);
    v.y = (v.y > 0.0f) ? v.y : expm1f(v.y);
    v.z = (v.z > 0.0f) ? v.z : expm1f(v.z);
    v.w = (v.w > 0.0f) ? v.w : expm1f(v.w);
    ((float4*)out)[i] = v;
}

extern "C" void kernel_launch(void* const* d_in, const int* in_sizes, int n_in,
                              void* d_out, int out_size) {
    const float* X   = (const float*)d_in[0];
    const int*   EI  = (const int*)d_in[1];      // int32 edge_index [2, E]
    const float* Wg  = (const float*)d_in[2];
    const float* A   = (const float*)d_in[3];
    float*       out = (float*)d_out;

    int N = in_sizes[0] / IN_DIM;   // 50000
    int E = in_sizes[1] / 2;        // 800000

    cudaMemsetAsync(d_out, 0, (size_t)out_size * sizeof(float));
    init_kernel<<<(N + 255) / 256, 256>>>(N);

    cudaFuncSetAttribute(gemm_kernel,
                         cudaFuncAttributeMaxDynamicSharedMemorySize,
                         GEMM_SMEM_BYTES);
    gemm_kernel<<<(N + 63) / 64, 256, GEMM_SMEM_BYTES>>>(X, Wg, N);

    score_kernel<<<(unsigned)(((size_t)N * 32 + 255) / 256), 256>>>(A, N);

    edge1_kernel<<<(E + 255) / 256, 256>>>(EI, E);
    edge2_kernel<<<(E + 255) / 256, 256>>>(EI, E);

    unsigned scatter_blocks = (unsigned)(((size_t)E * 16 + 255) / 256);
    edge3_kernel<<<scatter_blocks, 256>>>(EI, out, E);

    int n4 = N * OUT_DIM / 4;
    elu_kernel<<<(n4 + 255) / 256, 256>>>(out, n4);
}

// round 4
// speedup vs baseline: 1.2162x; 1.2162x over previous
#include <cuda_runtime.h>
#include <math_constants.h>

#define IN_DIM 128
#define OUT_DIM 64
#define MAX_N 50000
#define MAX_E 800000
#define ALPHA_LEAKY 0.2f
#define EPS_F 1e-10f

#define SCAN_CHUNK 1024

// ---- scratch (device globals; no allocation allowed) ----
__device__ float  g_h[(size_t)MAX_N * OUT_DIM];   // 12.8 MB
__device__ float  g_ssrc[MAX_N];
__device__ float  g_stgt[MAX_N];
__device__ int    g_deg[MAX_N];
__device__ int    g_rowptr[MAX_N + 1];
__device__ int    g_cursor[MAX_N];
__device__ int    g_bsum[(MAX_N + SCAN_CHUNK - 1) / SCAN_CHUNK];
__device__ float2 g_pack[MAX_E];                  // (leaky score, src-as-float-bits)

// ---------------------------------------------------------------------------
// zero degree counters
// ---------------------------------------------------------------------------
__global__ void zero_deg_kernel(int n) {
    int i = blockIdx.x * blockDim.x + threadIdx.x;
    if (i < n) g_deg[i] = 0;
}

// ---------------------------------------------------------------------------
// histogram of targets
// ---------------------------------------------------------------------------
__global__ void hist_kernel(const int* __restrict__ ei, int E) {
    int i = blockIdx.x * blockDim.x + threadIdx.x;
    if (i >= E) return;
    atomicAdd(&g_deg[__ldg(ei + E + i)], 1);
}

// ---------------------------------------------------------------------------
// exclusive scan, 3 phases (chunk=1024)
// ---------------------------------------------------------------------------
__global__ void __launch_bounds__(SCAN_CHUNK) scan1_kernel(int n) {
    __shared__ int wsum[32];
    int t = threadIdx.x, b = blockIdx.x;
    int gi = b * SCAN_CHUNK + t;
    int lane = t & 31, w = t >> 5;
    int v = (gi < n) ? g_deg[gi] : 0;
    int x = v;
#pragma unroll
    for (int off = 1; off < 32; off <<= 1) {
        int y = __shfl_up_sync(0xffffffffu, x, off);
        if (lane >= off) x += y;
    }
    if (lane == 31) wsum[w] = x;
    __syncthreads();
    if (w == 0) {
        int s = wsum[lane];
#pragma unroll
        for (int off = 1; off < 32; off <<= 1) {
            int y = __shfl_up_sync(0xffffffffu, s, off);
            if (lane >= off) s += y;
        }
        wsum[lane] = s;
    }
    __syncthreads();
    int incl = x + ((w > 0) ? wsum[w - 1] : 0);
    if (gi < n) g_rowptr[gi] = incl - v;   // exclusive within block
    if (t == SCAN_CHUNK - 1) g_bsum[b] = incl;
}

__global__ void __launch_bounds__(SCAN_CHUNK) scan2_kernel(int nb) {
    __shared__ int wsum[32];
    int t = threadIdx.x;
    int lane = t & 31, w = t >> 5;
    int v = (t < nb) ? g_bsum[t] : 0;
    int x = v;
#pragma unroll
    for (int off = 1; off < 32; off <<= 1) {
        int y = __shfl_up_sync(0xffffffffu, x, off);
        if (lane >= off) x += y;
    }
    if (lane == 31) wsum[w] = x;
    __syncthreads();
    if (w == 0) {
        int s = wsum[lane];
#pragma unroll
        for (int off = 1; off < 32; off <<= 1) {
            int y = __shfl_up_sync(0xffffffffu, s, off);
            if (lane >= off) s += y;
        }
        wsum[lane] = s;
    }
    __syncthreads();
    int incl = x + ((w > 0) ? wsum[w - 1] : 0);
    if (t < nb) g_bsum[t] = incl - v;      // exclusive block offsets
}

__global__ void scan3_kernel(int n, int E) {
    int gi = blockIdx.x * blockDim.x + threadIdx.x;
    if (gi < n) {
        int r = g_rowptr[gi] + g_bsum[gi >> 10];
        g_rowptr[gi] = r;
        g_cursor[gi] = r;
    }
    if (gi == 0) g_rowptr[n] = E;
}

// ---------------------------------------------------------------------------
// GEMM: g_h[n][o] = sum_k X[n][k] * W[o][k]
// 64 nodes x 64 outs per block, 256 threads, 4x4 register tile per thread.
// ---------------------------------------------------------------------------
#define WT_PITCH (OUT_DIM + 4)   // 68
#define XS_PITCH (IN_DIM + 4)    // 132
#define GEMM_SMEM_BYTES ((IN_DIM * WT_PITCH + 64 * XS_PITCH) * (int)sizeof(float))

__global__ void __launch_bounds__(256) gemm_kernel(
    const float* __restrict__ X, const float* __restrict__ Wg, int N)
{
    extern __shared__ float sm[];
    float* Wt = sm;                              // [IN_DIM][WT_PITCH]
    float* Xs = sm + IN_DIM * WT_PITCH;          // [64][XS_PITCH]

    int t = threadIdx.x;

    for (int i = t; i < IN_DIM * OUT_DIM; i += 256) {
        int o = i >> 7;
        int k = i & 127;
        Wt[k * WT_PITCH + o] = Wg[i];
    }

    int n0 = blockIdx.x * 64;
    for (int i = t; i < 64 * 32; i += 256) {
        int n  = i >> 5;
        int kq = i & 31;
        int gn = n0 + n;
        float4 v = make_float4(0.f, 0.f, 0.f, 0.f);
        if (gn < N) v = ((const float4*)(X + (size_t)gn * IN_DIM))[kq];
        ((float4*)(Xs + n * XS_PITCH))[kq] = v;
    }
    __syncthreads();

    int oq = (t & 15);
    int nq = (t >> 4) * 4;

    float acc[4][4];
#pragma unroll
    for (int j = 0; j < 4; j++)
#pragma unroll
        for (int c = 0; c < 4; c++) acc[j][c] = 0.0f;

#pragma unroll 8
    for (int k = 0; k < IN_DIM; k++) {
        float4 w4 = ((const float4*)(Wt + k * WT_PITCH))[oq];
#pragma unroll
        for (int j = 0; j < 4; j++) {
            float x = Xs[(nq + j) * XS_PITCH + k];
            acc[j][0] = fmaf(x, w4.x, acc[j][0]);
            acc[j][1] = fmaf(x, w4.y, acc[j][1]);
            acc[j][2] = fmaf(x, w4.z, acc[j][2]);
            acc[j][3] = fmaf(x, w4.w, acc[j][3]);
        }
    }

#pragma unroll
    for (int j = 0; j < 4; j++) {
        int gn = n0 + nq + j;
        if (gn < N) {
            float4 v = make_float4(acc[j][0], acc[j][1], acc[j][2], acc[j][3]);
            ((float4*)(g_h + (size_t)gn * OUT_DIM))[oq] = v;
        }
    }
}

// ---------------------------------------------------------------------------
// per-node attention partial scores: one warp per node, shuffle reduce
// ---------------------------------------------------------------------------
__global__ void score_kernel(const float* __restrict__ a, int N) {
    int warp = (blockIdx.x * blockDim.x + threadIdx.x) >> 5;
    int lane = threadIdx.x & 31;
    if (warp >= N) return;
    const float* hr = g_h + (size_t)warp * OUT_DIM;
    float h0 = hr[lane];
    float h1 = hr[lane + 32];
    float ss = h0 * __ldg(a + lane)      + h1 * __ldg(a + lane + 32);
    float st = h0 * __ldg(a + 64 + lane) + h1 * __ldg(a + 96 + lane);
#pragma unroll
    for (int off = 16; off > 0; off >>= 1) {
        ss += __shfl_down_sync(0xffffffffu, ss, off);
        st += __shfl_down_sync(0xffffffffu, st, off);
    }
    if (lane == 0) {
        g_ssrc[warp] = ss;
        g_stgt[warp] = st;
    }
}

// ---------------------------------------------------------------------------
// CSR fill: compute leaky score, place (e, src) at cursor slot of its target
// ---------------------------------------------------------------------------
__global__ void fill_kernel(const int* __restrict__ ei, int E) {
    int i = blockIdx.x * blockDim.x + threadIdx.x;
    if (i >= E) return;
    int src = __ldg(ei + i);
    int tgt = __ldg(ei + E + i);
    float e = g_ssrc[src] + g_stgt[tgt];
    e = (e > 0.0f) ? e : (ALPHA_LEAKY * e);
    int pos = atomicAdd(&g_cursor[tgt], 1);
    g_pack[pos] = make_float2(e, __int_as_float(src));
}

// ---------------------------------------------------------------------------
// aggregate: one warp per target. Register softmax over its CSR segment,
// shuffle-broadcast (att, src), coalesced float2 gather of h[src], fused ELU.
// No atomics on the output; every output row written exactly once.
// ---------------------------------------------------------------------------
__global__ void __launch_bounds__(256) agg_kernel(float* __restrict__ out, int N) {
    int gw   = (blockIdx.x * blockDim.x + threadIdx.x) >> 5;
    int lane = threadIdx.x & 31;
    if (gw >= N) return;

    int beg = g_rowptr[gw];
    int end = g_rowptr[gw + 1];

    // phase 1: segment max and exp-sum
    float m = -CUDART_INF_F;
    for (int j = beg + lane; j < end; j += 32)
        m = fmaxf(m, g_pack[j].x);
#pragma unroll
    for (int off = 16; off > 0; off >>= 1)
        m = fmaxf(m, __shfl_xor_sync(0xffffffffu, m, off));

    float s = 0.0f;
    for (int j = beg + lane; j < end; j += 32)
        s += __expf(g_pack[j].x - m);
#pragma unroll
    for (int off = 16; off > 0; off >>= 1)
        s += __shfl_xor_sync(0xffffffffu, s, off);

    float inv = 1.0f / (s + EPS_F);

    // phase 2: weighted feature accumulation
    float2 acc = make_float2(0.0f, 0.0f);
    for (int base = beg; base < end; base += 32) {
        int j = base + lane;
        float att = 0.0f;
        int   src = 0;
        if (j < end) {
            float2 p = g_pack[j];
            att = __expf(p.x - m) * inv;
            src = __float_as_int(p.y);
        }
        int cnt = min(32, end - base);
        for (int k = 0; k < cnt; k++) {
            float a  = __shfl_sync(0xffffffffu, att, k);
            int   sk = __shfl_sync(0xffffffffu, src, k);
            float2 hv = ((const float2*)(g_h + (size_t)sk * OUT_DIM))[lane];
            acc.x = fmaf(a, hv.x, acc.x);
            acc.y = fmaf(a, hv.y, acc.y);
        }
    }

    float2 o;
    o.x = (acc.x > 0.0f) ? acc.x : expm1f(acc.x);
    o.y = (acc.y > 0.0f) ? acc.y : expm1f(acc.y);
    ((float2*)(out + (size_t)gw * OUT_DIM))[lane] = o;
}

extern "C" void kernel_launch(void* const* d_in, const int* in_sizes, int n_in,
                              void* d_out, int out_size) {
    const float* X   = (const float*)d_in[0];
    const int*   EI  = (const int*)d_in[1];      // int32 edge_index [2, E]
    const float* Wg  = (const float*)d_in[2];
    const float* A   = (const float*)d_in[3];
    float*       out = (float*)d_out;

    int N = in_sizes[0] / IN_DIM;   // 50000
    int E = in_sizes[1] / 2;        // 800000
    int nb = (N + SCAN_CHUNK - 1) / SCAN_CHUNK;

    // CSR build (independent of GEMM)
    zero_deg_kernel<<<(N + 255) / 256, 256>>>(N);
    hist_kernel<<<(E + 255) / 256, 256>>>(EI, E);
    scan1_kernel<<<nb, SCAN_CHUNK>>>(N);
    scan2_kernel<<<1, SCAN_CHUNK>>>(nb);
    scan3_kernel<<<(N + 255) / 256, 256>>>(N, E);

    // feature transform + scores
    cudaFuncSetAttribute(gemm_kernel,
                         cudaFuncAttributeMaxDynamicSharedMemorySize,
                         GEMM_SMEM_BYTES);
    gemm_kernel<<<(N + 63) / 64, 256, GEMM_SMEM_BYTES>>>(X, Wg, N);
    score_kernel<<<(unsigned)(((size_t)N * 32 + 255) / 256), 256>>>(A, N);

    // CSR fill + fused softmax/aggregate/ELU
    fill_kernel<<<(E + 255) / 256, 256>>>(EI, E);
    agg_kernel<<<(unsigned)(((size_t)N * 32 + 255) / 256), 256>>>(out, N);
}

// round 5
// speedup vs baseline: 1.3221x; 1.0870x over previous
#include <cuda_runtime.h>
#include <math_constants.h>

#define IN_DIM 128
#define OUT_DIM 64
#define MAX_N 50000
#define MAX_E 800000
#define ALPHA_LEAKY 0.2f
#define EPS_F 1e-10f

#define SCAN_CHUNK 1024

// ---- scratch (device globals; no allocation allowed) ----
__device__ float  g_h[(size_t)MAX_N * OUT_DIM];   // 12.8 MB
__device__ float  g_ssrc[MAX_N];
__device__ float  g_stgt[MAX_N];
__device__ int    g_deg[MAX_N];
__device__ int    g_rowptr[MAX_N + 1];
__device__ int    g_cursor[MAX_N];
__device__ int    g_bsum[(MAX_N + SCAN_CHUNK - 1) / SCAN_CHUNK];
__device__ float2 g_pack[MAX_E];                  // (leaky score, src-as-float-bits)

// ---------------------------------------------------------------------------
// histogram of targets
// ---------------------------------------------------------------------------
__global__ void hist_kernel(const int* __restrict__ ei, int E) {
    int i = blockIdx.x * blockDim.x + threadIdx.x;
    if (i >= E) return;
    atomicAdd(&g_deg[__ldg(ei + E + i)], 1);
}

// ---------------------------------------------------------------------------
// exclusive scan, 3 phases (chunk=1024)  [runs on side stream, hidden by GEMM]
// ---------------------------------------------------------------------------
__global__ void __launch_bounds__(SCAN_CHUNK) scan1_kernel(int n) {
    __shared__ int wsum[32];
    int t = threadIdx.x, b = blockIdx.x;
    int gi = b * SCAN_CHUNK + t;
    int lane = t & 31, w = t >> 5;
    int v = (gi < n) ? g_deg[gi] : 0;
    int x = v;
#pragma unroll
    for (int off = 1; off < 32; off <<= 1) {
        int y = __shfl_up_sync(0xffffffffu, x, off);
        if (lane >= off) x += y;
    }
    if (lane == 31) wsum[w] = x;
    __syncthreads();
    if (w == 0) {
        int s = wsum[lane];
#pragma unroll
        for (int off = 1; off < 32; off <<= 1) {
            int y = __shfl_up_sync(0xffffffffu, s, off);
            if (lane >= off) s += y;
        }
        wsum[lane] = s;
    }
    __syncthreads();
    int incl = x + ((w > 0) ? wsum[w - 1] : 0);
    if (gi < n) g_rowptr[gi] = incl - v;   // exclusive within block
    if (t == SCAN_CHUNK - 1) g_bsum[b] = incl;
}

__global__ void __launch_bounds__(SCAN_CHUNK) scan2_kernel(int nb) {
    __shared__ int wsum[32];
    int t = threadIdx.x;
    int lane = t & 31, w = t >> 5;
    int v = (t < nb) ? g_bsum[t] : 0;
    int x = v;
#pragma unroll
    for (int off = 1; off < 32; off <<= 1) {
        int y = __shfl_up_sync(0xffffffffu, x, off);
        if (lane >= off) x += y;
    }
    if (lane == 31) wsum[w] = x;
    __syncthreads();
    if (w == 0) {
        int s = wsum[lane];
#pragma unroll
        for (int off = 1; off < 32; off <<= 1) {
            int y = __shfl_up_sync(0xffffffffu, s, off);
            if (lane >= off) s += y;
        }
        wsum[lane] = s;
    }
    __syncthreads();
    int incl = x + ((w > 0) ? wsum[w - 1] : 0);
    if (t < nb) g_bsum[t] = incl - v;      // exclusive block offsets
}

__global__ void scan3_kernel(int n, int E) {
    int gi = blockIdx.x * blockDim.x + threadIdx.x;
    if (gi < n) {
        int r = g_rowptr[gi] + g_bsum[gi >> 10];
        g_rowptr[gi] = r;
        g_cursor[gi] = r;
    }
    if (gi == 0) g_rowptr[n] = E;
}

// ---------------------------------------------------------------------------
// GEMM + fused attention partial scores.
// g_h[n][o] = sum_k X[n][k]*W[o][k]; s_src[n]=h.a[0:64]; s_tgt[n]=h.a[64:128]
// 64 nodes x 64 outs per block, 256 threads, 4x4 register tile per thread.
// Score reduction: each 16-lane group holds one node's full row in acc;
// xor-shuffle reduce over the group, lane oq==0 writes.
// ---------------------------------------------------------------------------
#define WT_PITCH (OUT_DIM + 4)   // 68
#define XS_PITCH (IN_DIM + 4)    // 132
#define GEMM_SMEM_BYTES ((IN_DIM * WT_PITCH + 64 * XS_PITCH) * (int)sizeof(float))

__global__ void __launch_bounds__(256) gemm_kernel(
    const float* __restrict__ X, const float* __restrict__ Wg,
    const float* __restrict__ av, int N)
{
    extern __shared__ float sm[];
    float* Wt = sm;                              // [IN_DIM][WT_PITCH]
    float* Xs = sm + IN_DIM * WT_PITCH;          // [64][XS_PITCH]

    int t = threadIdx.x;

    for (int i = t; i < IN_DIM * OUT_DIM; i += 256) {
        int o = i >> 7;
        int k = i & 127;
        Wt[k * WT_PITCH + o] = Wg[i];
    }

    int n0 = blockIdx.x * 64;
    for (int i = t; i < 64 * 32; i += 256) {
        int n  = i >> 5;
        int kq = i & 31;
        int gn = n0 + n;
        float4 v = make_float4(0.f, 0.f, 0.f, 0.f);
        if (gn < N) v = ((const float4*)(X + (size_t)gn * IN_DIM))[kq];
        ((float4*)(Xs + n * XS_PITCH))[kq] = v;
    }
    __syncthreads();

    int oq = (t & 15);
    int nq = (t >> 4) * 4;

    float acc[4][4];
#pragma unroll
    for (int j = 0; j < 4; j++)
#pragma unroll
        for (int c = 0; c < 4; c++) acc[j][c] = 0.0f;

#pragma unroll 8
    for (int k = 0; k < IN_DIM; k++) {
        float4 w4 = ((const float4*)(Wt + k * WT_PITCH))[oq];
#pragma unroll
        for (int j = 0; j < 4; j++) {
            float x = Xs[(nq + j) * XS_PITCH + k];
            acc[j][0] = fmaf(x, w4.x, acc[j][0]);
            acc[j][1] = fmaf(x, w4.y, acc[j][1]);
            acc[j][2] = fmaf(x, w4.z, acc[j][2]);
            acc[j][3] = fmaf(x, w4.w, acc[j][3]);
        }
    }

    // write h
#pragma unroll
    for (int j = 0; j < 4; j++) {
        int gn = n0 + nq + j;
        if (gn < N) {
            float4 v = make_float4(acc[j][0], acc[j][1], acc[j][2], acc[j][3]);
            ((float4*)(g_h + (size_t)gn * OUT_DIM))[oq] = v;
        }
    }

    // fused scores: a[4oq..4oq+3] and a[64+4oq..]
    const float4* a4 = (const float4*)av;
    float4 a0 = __ldg(a4 + oq);
    float4 a1 = __ldg(a4 + 16 + oq);
    float ps[4], pt[4];
#pragma unroll
    for (int j = 0; j < 4; j++) {
        ps[j] = acc[j][0]*a0.x + acc[j][1]*a0.y + acc[j][2]*a0.z + acc[j][3]*a0.w;
        pt[j] = acc[j][0]*a1.x + acc[j][1]*a1.y + acc[j][2]*a1.z + acc[j][3]*a1.w;
    }
#pragma unroll
    for (int off = 1; off < 16; off <<= 1) {
#pragma unroll
        for (int j = 0; j < 4; j++) {
            ps[j] += __shfl_xor_sync(0xffffffffu, ps[j], off);
            pt[j] += __shfl_xor_sync(0xffffffffu, pt[j], off);
        }
    }
    if (oq == 0) {
#pragma unroll
        for (int j = 0; j < 4; j++) {
            int gn = n0 + nq + j;
            if (gn < N) {
                g_ssrc[gn] = ps[j];
                g_stgt[gn] = pt[j];
            }
        }
    }
}

// ---------------------------------------------------------------------------
// CSR fill: compute leaky score, place (e, src) at cursor slot of its target
// ---------------------------------------------------------------------------
__global__ void fill_kernel(const int* __restrict__ ei, int E) {
    int i = blockIdx.x * blockDim.x + threadIdx.x;
    if (i >= E) return;
    int src = __ldg(ei + i);
    int tgt = __ldg(ei + E + i);
    float e = g_ssrc[src] + g_stgt[tgt];
    e = (e > 0.0f) ? e : (ALPHA_LEAKY * e);
    int pos = atomicAdd(&g_cursor[tgt], 1);
    g_pack[pos] = make_float2(e, __int_as_float(src));
}

// ---------------------------------------------------------------------------
// aggregate: one warp per target. Register softmax over its CSR segment,
// shuffle-broadcast (att, src), coalesced float2 gather of h[src], fused ELU.
// ---------------------------------------------------------------------------
__global__ void __launch_bounds__(256) agg_kernel(float* __restrict__ out, int N) {
    int gw   = (blockIdx.x * blockDim.x + threadIdx.x) >> 5;
    int lane = threadIdx.x & 31;
    if (gw >= N) return;

    int beg = g_rowptr[gw];
    int end = g_rowptr[gw + 1];

    float m = -CUDART_INF_F;
    for (int j = beg + lane; j < end; j += 32)
        m = fmaxf(m, g_pack[j].x);
#pragma unroll
    for (int off = 16; off > 0; off >>= 1)
        m = fmaxf(m, __shfl_xor_sync(0xffffffffu, m, off));

    float s = 0.0f;
    for (int j = beg + lane; j < end; j += 32)
        s += __expf(g_pack[j].x - m);
#pragma unroll
    for (int off = 16; off > 0; off >>= 1)
        s += __shfl_xor_sync(0xffffffffu, s, off);

    float inv = 1.0f / (s + EPS_F);

    float2 acc = make_float2(0.0f, 0.0f);
    for (int base = beg; base < end; base += 32) {
        int j = base + lane;
        float att = 0.0f;
        int   src = 0;
        if (j < end) {
            float2 p = g_pack[j];
            att = __expf(p.x - m) * inv;
            src = __float_as_int(p.y);
        }
        int cnt = min(32, end - base);
        for (int k = 0; k < cnt; k++) {
            float a  = __shfl_sync(0xffffffffu, att, k);
            int   sk = __shfl_sync(0xffffffffu, src, k);
            float2 hv = ((const float2*)(g_h + (size_t)sk * OUT_DIM))[lane];
            acc.x = fmaf(a, hv.x, acc.x);
            acc.y = fmaf(a, hv.y, acc.y);
        }
    }

    float2 o;
    o.x = (acc.x > 0.0f) ? acc.x : expm1f(acc.x);
    o.y = (acc.y > 0.0f) ? acc.y : expm1f(acc.y);
    ((float2*)(out + (size_t)gw * OUT_DIM))[lane] = o;
}

extern "C" void kernel_launch(void* const* d_in, const int* in_sizes, int n_in,
                              void* d_out, int out_size) {
    const float* X   = (const float*)d_in[0];
    const int*   EI  = (const int*)d_in[1];      // int32 edge_index [2, E]
    const float* Wg  = (const float*)d_in[2];
    const float* A   = (const float*)d_in[3];
    float*       out = (float*)d_out;

    int N = in_sizes[0] / IN_DIM;   // 50000
    int E = in_sizes[1] / 2;        // 800000
    int nb = (N + SCAN_CHUNK - 1) / SCAN_CHUNK;

    // one-time host-side resources (created on the uncaptured correctness call;
    // no device memory is allocated here)
    static cudaStream_t s2 = nullptr;
    static cudaEvent_t  e0 = nullptr, e1 = nullptr;
    static void* deg_ptr = nullptr;
    if (s2 == nullptr) {
        cudaStreamCreateWithFlags(&s2, cudaStreamNonBlocking);
        cudaEventCreateWithFlags(&e0, cudaEventDisableTiming);
        cudaEventCreateWithFlags(&e1, cudaEventDisableTiming);
        cudaGetSymbolAddress(&deg_ptr, g_deg);
        cudaFuncSetAttribute(gemm_kernel,
                             cudaFuncAttributeMaxDynamicSharedMemorySize,
                             GEMM_SMEM_BYTES);
    }

    // fork CSR-build chain onto side stream (overlaps with GEMM)
    cudaEventRecord(e0, (cudaStream_t)0);
    cudaStreamWaitEvent(s2, e0, 0);
    cudaMemsetAsync(deg_ptr, 0, (size_t)N * sizeof(int), s2);
    hist_kernel<<<(E + 255) / 256, 256, 0, s2>>>(EI, E);
    scan1_kernel<<<nb, SCAN_CHUNK, 0, s2>>>(N);
    scan2_kernel<<<1, SCAN_CHUNK, 0, s2>>>(nb);
    scan3_kernel<<<(N + 255) / 256, 256, 0, s2>>>(N, E);
    cudaEventRecord(e1, s2);

    // main chain: GEMM (+fused scores) on capture stream
    gemm_kernel<<<(N + 63) / 64, 256, GEMM_SMEM_BYTES>>>(X, Wg, A, N);

    // join: fill needs scores (main) + cursor/rowptr (side)
    cudaStreamWaitEvent((cudaStream_t)0, e1, 0);
    fill_kernel<<<(E + 255) / 256, 256>>>(EI, E);
    agg_kernel<<<(unsigned)(((size_t)N * 32 + 255) / 256), 256>>>(out, N);
}